// round 14
// baseline (speedup 1.0000x reference)
#include <cuda_runtime.h>
#include <cuda_fp16.h>
#include <cstdint>

#define HIDN   2048
#define NH     16
#define NKV    4
#define HD     128
#define INTERN 8192
#define BATCH  4
#define SEQ    1024
#define TTOK   (BATCH*SEQ)
#define EPSV   1e-6f
#define QK_SCALE 0.08838834764831845f
#define QKV_LD (NH*HD + 2*NKV*HD)      /* 3072 */

// ---------------- scratch ----------------
__device__ __half g_h16   [TTOK * HIDN];
__device__ __half g_qkv16 [TTOK * QKV_LD];
__device__ __half g_attn16[TTOK * HIDN];
__device__ float  g_x1    [TTOK * HIDN];
__device__ __half g_act16 [TTOK * INTERN];
__device__ __half g_wqkv16[QKV_LD * HIDN];
__device__ __half g_wo16  [HIDN * HIDN];
__device__ __half g_wgu16 [2 * INTERN * HIDN];   // row-interleaved: g_j->2j, u_j->2j+1
__device__ __half g_wd16  [HIDN * INTERN];
__device__ float  g_bqkv  [QKV_LD];

// ---------------- helpers ----------------
__device__ __forceinline__ void mma_f16(float c[4], const uint32_t a[4], const uint32_t b[2]) {
    asm volatile("mma.sync.aligned.m16n8k16.row.col.f32.f16.f16.f32 "
        "{%0,%1,%2,%3}, {%4,%5,%6,%7}, {%8,%9}, {%0,%1,%2,%3};\n"
        : "+f"(c[0]), "+f"(c[1]), "+f"(c[2]), "+f"(c[3])
        : "r"(a[0]), "r"(a[1]), "r"(a[2]), "r"(a[3]), "r"(b[0]), "r"(b[1]));
}
__device__ __forceinline__ uint32_t pack_h2(float lo, float hi) {
    __half2 h = __floats2half2_rn(lo, hi);
    return *(uint32_t*)&h;
}

#define CP16(dst, src) \
    asm volatile("cp.async.cg.shared.global [%0], [%1], 16;" :: "r"(dst), "l"(src))
#define CP_COMMIT() asm volatile("cp.async.commit_group;")
#define CP_WAIT(n)  asm volatile("cp.async.wait_group %0;" :: "n"(n))

// ---------------- fp16 GEMM, cp.async 4-stage ----------------
// MODE 0: float C (+bias)(+res). MODE 1: half C (+bias). MODE 2: half C = silu/up pair fuse.
#define STAGES 4
#define STAGE_BYTES 20480
#define GEMM_SMEM_BYTES (STAGES * STAGE_BYTES)

template<int MODE>
__device__ __forceinline__ void gemm_core(
    const __half* __restrict__ A, const __half* __restrict__ B,
    const float* __restrict__ bias, const float* __restrict__ res,
    void* __restrict__ Cv, int ldc, int K)
{
    extern __shared__ uint8_t smem_raw[];
    const int tid  = threadIdx.x;
    const int lane = tid & 31, warp = tid >> 5;
    const int wm = warp & 1, wn = warp >> 1;
    const int g  = lane >> 2, t4 = lane & 3;
    const int brow = blockIdx.y << 7, bcol = blockIdx.x << 7;

    const int ar = tid >> 2, achk = tid & 3;
    const __half* ag0 = A + (size_t)(brow + ar) * K + achk * 8;
    const __half* ag1 = ag0 + (size_t)64 * K;
    const __half* bg0 = B + (size_t)(bcol + ar) * K + achk * 8;
    const __half* bg1 = bg0 + (size_t)64 * K;

    const uint32_t sbase = (uint32_t)__cvta_generic_to_shared(smem_raw);
    const uint32_t sA0 = ar * 80 + achk * 16;
    const uint32_t sA1 = sA0 + 64 * 80;
    const uint32_t sB0 = 10240 + sA0;
    const uint32_t sB1 = 10240 + sA1;

    float acc[4][4][4];
#pragma unroll
    for (int i = 0; i < 4; i++)
#pragma unroll
        for (int j = 0; j < 4; j++)
#pragma unroll
            for (int e = 0; e < 4; e++) acc[i][j][e] = 0.f;

    const int nk = K >> 5;

#pragma unroll
    for (int s = 0; s < STAGES - 1; ++s) {
        uint32_t st = sbase + s * STAGE_BYTES;
        CP16(st + sA0, ag0 + s * 32);
        CP16(st + sA1, ag1 + s * 32);
        CP16(st + sB0, bg0 + s * 32);
        CP16(st + sB1, bg1 + s * 32);
        CP_COMMIT();
    }

    for (int t = 0; t < nk; ++t) {
        CP_WAIT(STAGES - 2);
        __syncthreads();
        const int tn = t + STAGES - 1;
        if (tn < nk) {
            uint32_t st = sbase + (tn & (STAGES - 1)) * STAGE_BYTES;
            CP16(st + sA0, ag0 + tn * 32);
            CP16(st + sA1, ag1 + tn * 32);
            CP16(st + sB0, bg0 + tn * 32);
            CP16(st + sB1, bg1 + tn * 32);
            CP_COMMIT();
        }
        const uint32_t* As_ = (const uint32_t*)(smem_raw + (t & (STAGES - 1)) * STAGE_BYTES);
        const uint32_t* Bs_ = As_ + 2560;
#pragma unroll
        for (int kb = 0; kb < 16; kb += 8) {
            uint32_t af[4][4], bf[4][2];
#pragma unroll
            for (int mt = 0; mt < 4; ++mt) {
                int base = (wm * 64 + mt * 16 + g) * 20 + kb + t4;
                af[mt][0] = As_[base];
                af[mt][1] = As_[base + 160];
                af[mt][2] = As_[base + 4];
                af[mt][3] = As_[base + 164];
            }
#pragma unroll
            for (int nt = 0; nt < 4; ++nt) {
                int nbase = (wn * 32 + nt * 8 + g) * 20 + kb + t4;
                bf[nt][0] = Bs_[nbase];
                bf[nt][1] = Bs_[nbase + 4];
            }
#pragma unroll
            for (int mt = 0; mt < 4; ++mt)
#pragma unroll
                for (int nt = 0; nt < 4; ++nt)
                    mma_f16(acc[mt][nt], af[mt], bf[nt]);
        }
    }

#pragma unroll
    for (int mt = 0; mt < 4; ++mt) {
        int r0 = brow + wm * 64 + mt * 16 + g;
#pragma unroll
        for (int nt = 0; nt < 4; ++nt) {
            int c0 = bcol + wn * 32 + nt * 8 + t4 * 2;
            float2 v0 = make_float2(acc[mt][nt][0], acc[mt][nt][1]);
            float2 v1 = make_float2(acc[mt][nt][2], acc[mt][nt][3]);
            if (MODE == 2) {
                __half* A16 = (__half*)Cv;
                int j0 = c0 >> 1;
                float a0 = v0.x / (1.f + __expf(-v0.x)) * v0.y;
                float a1 = v1.x / (1.f + __expf(-v1.x)) * v1.y;
                A16[(size_t)r0 * ldc + j0]       = __float2half(a0);
                A16[(size_t)(r0 + 8) * ldc + j0] = __float2half(a1);
            } else {
                if (bias) {
                    float2 bv = *(const float2*)&bias[c0];
                    v0.x += bv.x; v0.y += bv.y; v1.x += bv.x; v1.y += bv.y;
                }
                if (MODE == 1) {
                    __half* C16 = (__half*)Cv;
                    *(uint32_t*)&C16[(size_t)r0 * ldc + c0]       = pack_h2(v0.x, v0.y);
                    *(uint32_t*)&C16[(size_t)(r0 + 8) * ldc + c0] = pack_h2(v1.x, v1.y);
                } else {
                    float* C = (float*)Cv;
                    if (res) {
                        float2 ra = *(const float2*)&res[(size_t)r0 * ldc + c0];
                        float2 rb = *(const float2*)&res[(size_t)(r0 + 8) * ldc + c0];
                        v0.x += ra.x; v0.y += ra.y; v1.x += rb.x; v1.y += rb.y;
                    }
                    *(float2*)&C[(size_t)r0 * ldc + c0]       = v0;
                    *(float2*)&C[(size_t)(r0 + 8) * ldc + c0] = v1;
                }
            }
        }
    }
}

__global__ __launch_bounds__(256, 2)
void gemm_f16(const __half* __restrict__ A, const __half* __restrict__ B,
              const float* __restrict__ bias, const float* __restrict__ res,
              float* __restrict__ C, int ldc, int K) {
    gemm_core<0>(A, B, bias, res, C, ldc, K);
}
__global__ __launch_bounds__(256, 2)
void gemm_f16_qkv(const __half* __restrict__ A, const __half* __restrict__ B,
                  const float* __restrict__ bias, __half* __restrict__ C, int ldc, int K) {
    gemm_core<1>(A, B, bias, nullptr, C, ldc, K);
}
__global__ __launch_bounds__(256, 2)
void gemm_f16_silu(const __half* __restrict__ A, const __half* __restrict__ B,
                   __half* __restrict__ C, int ldc, int K) {
    gemm_core<2>(A, B, nullptr, nullptr, C, ldc, K);
}

// ---------------- fp32 -> fp16 convert ----------------
__global__ void cvt16_kernel(const float* __restrict__ src, __half* __restrict__ dst, int n16) {
    int i = blockIdx.x * blockDim.x + threadIdx.x;
    if (i >= n16) return;
#pragma unroll
    for (int h = 0; h < 2; h++) {
        float4 a = ((const float4*)src)[4 * i + 2 * h];
        float4 b = ((const float4*)src)[4 * i + 2 * h + 1];
        uint4 o;
        o.x = pack_h2(a.x, a.y); o.y = pack_h2(a.z, a.w);
        o.z = pack_h2(b.x, b.y); o.w = pack_h2(b.z, b.w);
        ((uint4*)dst)[2 * i + h] = o;
    }
}
// interleaved gate/up in one launch: src row j -> dst row 2j (gate) / 2j+1 (up)
__global__ void cvt16_gu_kernel(const float* __restrict__ wg, const float* __restrict__ wu,
                                __half* __restrict__ dst, int Kc, int n8) {
    int i = blockIdx.x * blockDim.x + threadIdx.x;
    int off = 0;
    const float* src = wg;
    if (i >= n8) { i -= n8; off = 1; src = wu; }
    if (i >= n8) return;
    int row = i / Kc, cj = i - row * Kc;
    float4 a = ((const float4*)src)[2 * i];
    float4 b = ((const float4*)src)[2 * i + 1];
    uint4 o;
    o.x = pack_h2(a.x, a.y); o.y = pack_h2(a.z, a.w);
    o.z = pack_h2(b.x, b.y); o.w = pack_h2(b.z, b.w);
    ((uint4*)dst)[(size_t)(2 * row + off) * Kc + cj] = o;
}

__global__ void pack_bias_kernel(const float* __restrict__ bq, const float* __restrict__ bk,
                                 const float* __restrict__ bv, float* __restrict__ dst) {
    int i = blockIdx.x * blockDim.x + threadIdx.x;
    if (i < QKV_LD)
        dst[i] = (i < 2048) ? bq[i] : ((i < 2560) ? bk[i - 2048] : bv[i - 2560]);
}

// ---------------- RMSNorm -> fp16 ----------------
__global__ void rmsnorm16_kernel(const float* __restrict__ x, const float* __restrict__ w,
                                 __half* __restrict__ out) {
    int row = blockIdx.x;
    const float* xr = x + (size_t)row * HIDN;
    float4 v[2];
    float ss = 0.f;
#pragma unroll
    for (int i = 0; i < 2; i++) {
        v[i] = *(const float4*)&xr[(threadIdx.x + i * 256) * 4];
        ss += v[i].x * v[i].x + v[i].y * v[i].y + v[i].z * v[i].z + v[i].w * v[i].w;
    }
#pragma unroll
    for (int o = 16; o; o >>= 1) ss += __shfl_xor_sync(~0u, ss, o);
    __shared__ float red[8];
    if ((threadIdx.x & 31) == 0) red[threadIdx.x >> 5] = ss;
    __syncthreads();
    if (threadIdx.x == 0) {
        float t = 0.f;
#pragma unroll
        for (int i = 0; i < 8; i++) t += red[i];
        red[0] = rsqrtf(t / (float)HIDN + EPSV);
    }
    __syncthreads();
    float r = red[0];
#pragma unroll
    for (int i = 0; i < 2; i++) {
        int c = (threadIdx.x + i * 256) * 4;
        float4 wv = *(const float4*)&w[c];
        uint2 o2;
        o2.x = pack_h2(v[i].x * r * wv.x, v[i].y * r * wv.y);
        o2.y = pack_h2(v[i].z * r * wv.z, v[i].w * r * wv.w);
        *(uint2*)&out[(size_t)row * HIDN + c] = o2;
    }
}

// ---------------- per-head RMSNorm + RoPE on fp16 qkv (q pre-scaled) ----------------
__global__ void qknorm_rope16_kernel(__half* __restrict__ qkv,
                                     const float* __restrict__ qw, const float* __restrict__ kw,
                                     const float* __restrict__ cs, const float* __restrict__ sn) {
    int token = blockIdx.x, h = blockIdx.y;
    __half* p; const float* w; float oscale;
    if (h < NH) { p = qkv + (size_t)token * QKV_LD + h * HD;               w = qw; oscale = QK_SCALE; }
    else        { p = qkv + (size_t)token * QKV_LD + 2048 + (h - NH) * HD; w = kw; oscale = 1.f; }
    int d = threadIdx.x;
    float v = __half2float(p[d]);
    float ss = v * v;
#pragma unroll
    for (int o = 16; o; o >>= 1) ss += __shfl_xor_sync(~0u, ss, o);
    __shared__ float red[4];
    __shared__ float sh[128];
    if ((d & 31) == 0) red[d >> 5] = ss;
    __syncthreads();
    float tot = red[0] + red[1] + red[2] + red[3];
    float r = rsqrtf(tot / 128.f + EPSV);
    float xn = v * r * w[d];
    sh[d] = xn;
    __syncthreads();
    float rot = (d < 64) ? -sh[d + 64] : sh[d - 64];
    float c = cs[(size_t)token * 128 + d], s = sn[(size_t)token * 128 + d];
    p[d] = __float2half((xn * c + rot * s) * oscale);
}

// ---------------- flash attention (fp16 MMA, Q-tile 128, causal, GQA) ----------------
// 512 thr = 16 warps: 8(M, 16 rows) x 2(N). k-tile 64.
#define AQK_STRIDE 68
#define AV_STRIDE  136
#define AP_STRIDE  36
#define ATTN_U32  (128*AQK_STRIDE + 64*AQK_STRIDE + 32*AV_STRIDE + 128*AP_STRIDE + 2*128 + 2*128 + 3*128)
#define ATTN_SMEM_BYTES (ATTN_U32 * 4)

__global__ __launch_bounds__(512, 1)
void attn_kernel(const __half* __restrict__ qkv, __half* __restrict__ o16) {
    extern __shared__ uint32_t smem[];
    uint32_t* Qs = smem;                         // 128 x 68
    uint32_t* Ks = Qs + 128 * AQK_STRIDE;        // 64 x 68
    uint32_t* Vs = Ks + 64 * AQK_STRIDE;         // 32 x 136 (k-pair packed)
    uint32_t* Ps = Vs + 32 * AV_STRIDE;          // 128 x 36
    float* Pmax = (float*)(Ps + 128 * AP_STRIDE);// [2][128]
    float* Psum = Pmax + 256;                    // [2][128]
    float* Mrow = Psum + 256;
    float* Lrow = Mrow + 128;
    float* Arow = Lrow + 128;

    const int tid  = threadIdx.x;
    const int lane = tid & 31, warp = tid >> 5;
    const int wm = warp & 7, wn = warp >> 3;
    const int g = lane >> 2, t4 = lane & 3;
    const int qt = blockIdx.x, hq = blockIdx.y, b = blockIdx.z;
    const int kvh = hq >> 2;
    const int tok0 = b * SEQ + qt * 128;
    const int r0 = wm * 16 + g, r1 = r0 + 8;

    // Q tile: 128 rows x 16 uint4 chunks (pre-scaled fp16)
    for (int l = tid; l < 128 * 16; l += 512) {
        int r = l >> 4, c = (l & 15);
        uint4 qv = *(const uint4*)&qkv[(size_t)(tok0 + r) * QKV_LD + hq * HD + c * 8];
        *(uint4*)&Qs[r * AQK_STRIDE + c * 4] = qv;
    }
    if (tid < 128) { Mrow[tid] = -3.0e38f; Lrow[tid] = 0.f; }

    float O[8][4];
#pragma unroll
    for (int nt = 0; nt < 8; nt++)
#pragma unroll
        for (int e = 0; e < 4; e++) O[nt][e] = 0.f;
    __syncthreads();

    const int nkt = 2 * qt + 2;
    for (int kt = 0; kt < nkt; ++kt) {
        for (int l = tid; l < 64 * 16; l += 512) {
            int r = l >> 4, c = (l & 15);
            uint4 kv = *(const uint4*)&qkv[(size_t)(b * SEQ + kt * 64 + r) * QKV_LD + 2048 + kvh * HD + c * 8];
            *(uint4*)&Ks[r * AQK_STRIDE + c * 4] = kv;
        }
        for (int l = tid; l < 32 * 16; l += 512) {
            int r = l >> 4, c = (l & 15);
            size_t base = (size_t)(b * SEQ + kt * 64 + 2 * r) * QKV_LD + 2560 + kvh * HD + c * 8;
            uint4 va = *(const uint4*)&qkv[base];
            uint4 vb = *(const uint4*)&qkv[base + QKV_LD];
            uint4 o0, o1;
            o0.x = __byte_perm(va.x, vb.x, 0x5410); o0.y = __byte_perm(va.x, vb.x, 0x7632);
            o0.z = __byte_perm(va.y, vb.y, 0x5410); o0.w = __byte_perm(va.y, vb.y, 0x7632);
            o1.x = __byte_perm(va.z, vb.z, 0x5410); o1.y = __byte_perm(va.z, vb.z, 0x7632);
            o1.z = __byte_perm(va.w, vb.w, 0x5410); o1.w = __byte_perm(va.w, vb.w, 0x7632);
            *(uint4*)&Vs[r * AV_STRIDE + c * 8]     = o0;
            *(uint4*)&Vs[r * AV_STRIDE + c * 8 + 4] = o1;
        }
        __syncthreads();

        // ---- S = Q K^T (warp tile 16 x 32) ----
        float s[4][4];
#pragma unroll
        for (int nt = 0; nt < 4; nt++)
#pragma unroll
            for (int e = 0; e < 4; e++) s[nt][e] = 0.f;
        {
            const int arow0 = r0 * AQK_STRIDE, arow1 = r1 * AQK_STRIDE;
#pragma unroll
            for (int kb = 0; kb < 64; kb += 8) {
                uint32_t a[4];
                a[0] = Qs[arow0 + kb + t4];
                a[1] = Qs[arow1 + kb + t4];
                a[2] = Qs[arow0 + kb + t4 + 4];
                a[3] = Qs[arow1 + kb + t4 + 4];
#pragma unroll
                for (int nt = 0; nt < 4; nt++) {
                    uint32_t bb[2];
                    int nb = (wn * 32 + nt * 8 + g) * AQK_STRIDE + kb + t4;
                    bb[0] = Ks[nb]; bb[1] = Ks[nb + 4];
                    mma_f16(s[nt], a, bb);
                }
            }
        }

        // causal mask: only tiles kt >= 2qt touch the diagonal
        if (kt >= 2 * qt) {
            const int dq = (2 * qt - kt) * 64;   // 0 or -64
#pragma unroll
            for (int nt = 0; nt < 4; nt++) {
                int c0 = wn * 32 + nt * 8 + 2 * t4;
                if (c0     > r0 + dq) s[nt][0] = -1.0e30f;
                if (c0 + 1 > r0 + dq) s[nt][1] = -1.0e30f;
                if (c0     > r1 + dq) s[nt][2] = -1.0e30f;
                if (c0 + 1 > r1 + dq) s[nt][3] = -1.0e30f;
            }
        }

        {
            float mx0 = fmaxf(fmaxf(s[0][0], s[0][1]), fmaxf(s[1][0], s[1][1]));
            mx0 = fmaxf(mx0, fmaxf(fmaxf(s[2][0], s[2][1]), fmaxf(s[3][0], s[3][1])));
            float mx1 = fmaxf(fmaxf(s[0][2], s[0][3]), fmaxf(s[1][2], s[1][3]));
            mx1 = fmaxf(mx1, fmaxf(fmaxf(s[2][2], s[2][3]), fmaxf(s[3][2], s[3][3])));
            mx0 = fmaxf(mx0, __shfl_xor_sync(~0u, mx0, 1));
            mx0 = fmaxf(mx0, __shfl_xor_sync(~0u, mx0, 2));
            mx1 = fmaxf(mx1, __shfl_xor_sync(~0u, mx1, 1));
            mx1 = fmaxf(mx1, __shfl_xor_sync(~0u, mx1, 2));
            if (t4 == 0) { Pmax[wn * 128 + r0] = mx0; Pmax[wn * 128 + r1] = mx1; }
        }
        __syncthreads();

        {
            float mn0 = fmaxf(Mrow[r0], fmaxf(Pmax[r0], Pmax[128 + r0]));
            float mn1 = fmaxf(Mrow[r1], fmaxf(Pmax[r1], Pmax[128 + r1]));
            float sum0 = 0.f, sum1 = 0.f;
#pragma unroll
            for (int nt = 0; nt < 4; nt++) {
                int cu = wn * 16 + nt * 4 + t4;
                float p0 = __expf(s[nt][0] - mn0);
                float p1 = __expf(s[nt][1] - mn0);
                float p2 = __expf(s[nt][2] - mn1);
                float p3 = __expf(s[nt][3] - mn1);
                sum0 += p0 + p1; sum1 += p2 + p3;
                Ps[r0 * AP_STRIDE + cu] = pack_h2(p0, p1);
                Ps[r1 * AP_STRIDE + cu] = pack_h2(p2, p3);
            }
            sum0 += __shfl_xor_sync(~0u, sum0, 1);
            sum0 += __shfl_xor_sync(~0u, sum0, 2);
            sum1 += __shfl_xor_sync(~0u, sum1, 1);
            sum1 += __shfl_xor_sync(~0u, sum1, 2);
            if (t4 == 0) { Psum[wn * 128 + r0] = sum0; Psum[wn * 128 + r1] = sum1; }
        }
        __syncthreads();

        if (tid < 128) {
            int r = tid;
            float mo = Mrow[r];
            float mn = fmaxf(mo, fmaxf(Pmax[r], Pmax[128 + r]));
            float al = __expf(mo - mn);
            Lrow[r] = Lrow[r] * al + Psum[r] + Psum[128 + r];
            Mrow[r] = mn;
            Arow[r] = al;
        }
        __syncthreads();

        // ---- O += P V (warp tile 16 x 64 of d=128, wn picks d-half) ----
        {
            float al0 = Arow[r0], al1 = Arow[r1];
#pragma unroll
            for (int nt = 0; nt < 8; nt++) {
                O[nt][0] *= al0; O[nt][1] *= al0;
                O[nt][2] *= al1; O[nt][3] *= al1;
            }
            const int prow0 = r0 * AP_STRIDE, prow1 = r1 * AP_STRIDE;
#pragma unroll
            for (int kb = 0; kb < 32; kb += 8) {
                uint32_t a[4];
                a[0] = Ps[prow0 + kb + t4];
                a[1] = Ps[prow1 + kb + t4];
                a[2] = Ps[prow0 + kb + t4 + 4];
                a[3] = Ps[prow1 + kb + t4 + 4];
#pragma unroll
                for (int nt = 0; nt < 8; nt++) {
                    uint32_t bb[2];
                    int col = wn * 64 + nt * 8 + g;
                    bb[0] = Vs[(kb + t4) * AV_STRIDE + col];
                    bb[1] = Vs[(kb + t4 + 4) * AV_STRIDE + col];
                    mma_f16(O[nt], a, bb);
                }
            }
        }
        __syncthreads();
    }

    {
        float inv0 = 1.f / Lrow[r0], inv1 = 1.f / Lrow[r1];
        size_t base0 = (size_t)(tok0 + r0) * (NH * HD) + hq * HD;
        size_t base1 = (size_t)(tok0 + r1) * (NH * HD) + hq * HD;
#pragma unroll
        for (int nt = 0; nt < 8; nt++) {
            int c = wn * 64 + nt * 8 + 2 * t4;
            *(uint32_t*)&o16[base0 + c] = pack_h2(O[nt][0] * inv0, O[nt][1] * inv0);
            *(uint32_t*)&o16[base1 + c] = pack_h2(O[nt][2] * inv1, O[nt][3] * inv1);
        }
    }
}

// ---------------- host orchestration ----------------
extern "C" void kernel_launch(void* const* d_in, const int* in_sizes, int n_in,
                              void* d_out, int out_size) {
    const float* x    = (const float*)d_in[0];
    const float* cosb = (const float*)d_in[2];
    const float* sinb = (const float*)d_in[3];
    const float* wq   = (const float*)d_in[4];
    const float* bq   = (const float*)d_in[5];
    const float* wk   = (const float*)d_in[6];
    const float* bk   = (const float*)d_in[7];
    const float* wv   = (const float*)d_in[8];
    const float* bv   = (const float*)d_in[9];
    const float* wo   = (const float*)d_in[10];
    const float* qnw  = (const float*)d_in[11];
    const float* knw  = (const float*)d_in[12];
    const float* ln1  = (const float*)d_in[13];
    const float* ln2  = (const float*)d_in[14];
    const float* wg   = (const float*)d_in[15];
    const float* wu   = (const float*)d_in[16];
    const float* wd   = (const float*)d_in[17];
    float* out = (float*)d_out;

    __half *h16, *attn16, *act16, *wqkv16, *wo16, *wgu16, *wd16, *qkv16;
    float *x1_, *bqkv;
    cudaGetSymbolAddress((void**)&h16,    g_h16);
    cudaGetSymbolAddress((void**)&attn16, g_attn16);
    cudaGetSymbolAddress((void**)&act16,  g_act16);
    cudaGetSymbolAddress((void**)&wqkv16, g_wqkv16);
    cudaGetSymbolAddress((void**)&wo16,   g_wo16);
    cudaGetSymbolAddress((void**)&wgu16,  g_wgu16);
    cudaGetSymbolAddress((void**)&wd16,   g_wd16);
    cudaGetSymbolAddress((void**)&qkv16,  g_qkv16);
    cudaGetSymbolAddress((void**)&x1_,    g_x1);
    cudaGetSymbolAddress((void**)&bqkv,   g_bqkv);

    cudaFuncSetAttribute(attn_kernel,   cudaFuncAttributeMaxDynamicSharedMemorySize, ATTN_SMEM_BYTES);
    cudaFuncSetAttribute(gemm_f16,      cudaFuncAttributeMaxDynamicSharedMemorySize, GEMM_SMEM_BYTES);
    cudaFuncSetAttribute(gemm_f16_qkv,  cudaFuncAttributeMaxDynamicSharedMemorySize, GEMM_SMEM_BYTES);
    cudaFuncSetAttribute(gemm_f16_silu, cudaFuncAttributeMaxDynamicSharedMemorySize, GEMM_SMEM_BYTES);

    // 0. weight conversion / packing
    {
        const int T = 256;
        cvt16_kernel<<<(2048*2048/16 + T-1)/T, T>>>(wq, wqkv16,              2048*2048/16);
        cvt16_kernel<<<( 512*2048/16 + T-1)/T, T>>>(wk, wqkv16 + 2048*2048,   512*2048/16);
        cvt16_kernel<<<( 512*2048/16 + T-1)/T, T>>>(wv, wqkv16 + 2560*2048,   512*2048/16);
        cvt16_kernel<<<(2048*2048/16 + T-1)/T, T>>>(wo, wo16,                2048*2048/16);
        cvt16_gu_kernel<<<(2*8192*2048/8 + T-1)/T, T>>>(wg, wu, wgu16, 2048/8, 8192*2048/8);
        cvt16_kernel<<<(2048*8192/16 + T-1)/T, T>>>(wd, wd16,                2048*8192/16);
        pack_bias_kernel<<<(QKV_LD + T-1)/T, T>>>(bq, bk, bv, bqkv);
    }

    // 1. h16 = (half) RMSNorm(x, ln1)
    rmsnorm16_kernel<<<TTOK, 256>>>(x, ln1, h16);
    // 2. packed QKV projection -> fp16
    gemm_f16_qkv<<<dim3(QKV_LD/128, TTOK/128), 256, GEMM_SMEM_BYTES>>>(h16, wqkv16, bqkv, qkv16, QKV_LD, HIDN);
    // 3. per-head RMSNorm + RoPE (fp16, q pre-scaled by 1/sqrt(d))
    qknorm_rope16_kernel<<<dim3(TTOK, NH + NKV), 128>>>(qkv16, qnw, knw, cosb, sinb);
    // 4. causal flash attention, Q-tile 128 (fp16 MMA)
    attn_kernel<<<dim3(SEQ/128, NH, BATCH), 512, ATTN_SMEM_BYTES>>>(qkv16, attn16);
    // 5. x1 = x + attn @ wo^T
    gemm_f16<<<dim3(HIDN/128, TTOK/128), 256, GEMM_SMEM_BYTES>>>(attn16, wo16, nullptr, x, x1_, HIDN, HIDN);
    // 6. h16 = (half) RMSNorm(x1, ln2)
    rmsnorm16_kernel<<<TTOK, 256>>>(x1_, ln2, h16);
    // 7. fused gate|up projection + silu (interleaved weights) -> act16
    gemm_f16_silu<<<dim3(2*INTERN/128, TTOK/128), 256, GEMM_SMEM_BYTES>>>(h16, wgu16, act16, INTERN, HIDN);
    // 8. out = x1 + act @ wd^T
    gemm_f16<<<dim3(HIDN/128, TTOK/128), 256, GEMM_SMEM_BYTES>>>(act16, wd16, nullptr, x1_, out, HIDN, INTERN);
}

// round 15
// speedup vs baseline: 1.1959x; 1.1959x over previous
#include <cuda_runtime.h>
#include <cuda_fp16.h>
#include <cstdint>

#define HIDN   2048
#define NH     16
#define NKV    4
#define HD     128
#define INTERN 8192
#define BATCH  4
#define SEQ    1024
#define TTOK   (BATCH*SEQ)
#define EPSV   1e-6f
#define QK_SCALE 0.08838834764831845f
#define QKV_LD (NH*HD + 2*NKV*HD)      /* 3072 */

// ---------------- scratch ----------------
__device__ __half g_h16   [TTOK * HIDN];
__device__ __half g_qkv16 [TTOK * QKV_LD];
__device__ __half g_attn16[TTOK * HIDN];
__device__ float  g_x1    [TTOK * HIDN];
__device__ __half g_act16 [TTOK * INTERN];
// weights, TILED: [nb][kt] tiles of 128 rows x 32 halves (8KB), 16B-chunk swizzled
__device__ __half g_wqkv16[QKV_LD * HIDN];
__device__ __half g_wo16  [HIDN * HIDN];
__device__ __half g_wgu16 [2 * INTERN * HIDN];   // rows interleaved: g_j->2j, u_j->2j+1
__device__ __half g_wd16  [HIDN * INTERN];
__device__ float  g_bqkv  [QKV_LD];

// ---------------- helpers ----------------
__device__ __forceinline__ void mma_f16(float c[4], const uint32_t a[4], const uint32_t b[2]) {
    asm volatile("mma.sync.aligned.m16n8k16.row.col.f32.f16.f16.f32 "
        "{%0,%1,%2,%3}, {%4,%5,%6,%7}, {%8,%9}, {%0,%1,%2,%3};\n"
        : "+f"(c[0]), "+f"(c[1]), "+f"(c[2]), "+f"(c[3])
        : "r"(a[0]), "r"(a[1]), "r"(a[2]), "r"(a[3]), "r"(b[0]), "r"(b[1]));
}
__device__ __forceinline__ uint32_t pack_h2(float lo, float hi) {
    __half2 h = __floats2half2_rn(lo, hi);
    return *(uint32_t*)&h;
}
__device__ __forceinline__ uint32_t smem_u32(const void* p) {
    uint32_t a;
    asm("{ .reg .u64 t; cvta.to.shared.u64 t, %1; cvt.u32.u64 %0, t; }" : "=r"(a) : "l"(p));
    return a;
}
__device__ __forceinline__ void mbar_init(uint32_t a, uint32_t cnt) {
    asm volatile("mbarrier.init.shared.b64 [%0], %1;" :: "r"(a), "r"(cnt) : "memory");
}
__device__ __forceinline__ void mbar_expect(uint32_t a, uint32_t tx) {
    asm volatile("mbarrier.arrive.expect_tx.shared.b64 _, [%0], %1;" :: "r"(a), "r"(tx) : "memory");
}
__device__ __forceinline__ void mbar_wait(uint32_t a, uint32_t ph) {
    asm volatile("{\n\t.reg .pred P;\n"
        "LAB_%=:\n\t"
        "mbarrier.try_wait.parity.shared.b64 P, [%0], %1;\n\t"
        "@!P bra LAB_%=;\n\t}"
        :: "r"(a), "r"(ph) : "memory");
}
__device__ __forceinline__ void bulk_ld(uint32_t dst, const void* src, uint32_t bytes, uint32_t mbar) {
    asm volatile("cp.async.bulk.shared::cta.global.mbarrier::complete_tx::bytes [%0], [%1], %2, [%3];"
        :: "r"(dst), "l"(src), "r"(bytes), "r"(mbar) : "memory");
}

#define CP16(dst, src) \
    asm volatile("cp.async.cg.shared.global [%0], [%1], 16;" :: "r"(dst), "l"(src))
#define CP_COMMIT() asm volatile("cp.async.commit_group;")
#define CP_WAIT(n)  asm volatile("cp.async.wait_group %0;" :: "n"(n))

// ---------------- fp16 GEMM: cp.async A + bulk-B (tiled weights) ----------------
// MODE 0: float C (+bias)(+res). MODE 1: half C (+bias). MODE 2: half C = silu/up fuse.
#define STAGES 4
#define A_STAGE 10240
#define B_STAGE 8192
#define STAGE_BYTES (A_STAGE + B_STAGE)          /* 18432 */
#define GEMM_SMEM_BYTES (STAGES * STAGE_BYTES)   /* 73728 */

template<int MODE>
__device__ __forceinline__ void gemm_core(
    const __half* __restrict__ A, const __half* __restrict__ Bt,
    const float* __restrict__ bias, const float* __restrict__ res,
    void* __restrict__ Cv, int ldc, int K)
{
    extern __shared__ uint8_t smem_raw[];
    __shared__ uint64_t bbar[STAGES];
    const int tid  = threadIdx.x;
    const int lane = tid & 31, warp = tid >> 5;
    const int wm = warp & 1, wn = warp >> 1;
    const int g  = lane >> 2, t4 = lane & 3;
    const int brow = blockIdx.y << 7, bcol = blockIdx.x << 7;
    const int nkt = K >> 5;

    // A loader (linear gmem, padded smem stride 20)
    const int ar = tid >> 2, achk = tid & 3;
    const __half* ag0 = A + (size_t)(brow + ar) * K + achk * 8;
    const __half* ag1 = ag0 + (size_t)64 * K;
    const uint32_t sbase = (uint32_t)__cvta_generic_to_shared(smem_raw);
    const uint32_t sA0 = ar * 80 + achk * 16;
    const uint32_t sA1 = sA0 + 64 * 80;

    const __half* Btiles = Bt + (size_t)blockIdx.x * nkt * 4096;

    float acc[4][4][4];
#pragma unroll
    for (int i = 0; i < 4; i++)
#pragma unroll
        for (int j = 0; j < 4; j++)
#pragma unroll
            for (int e = 0; e < 4; e++) acc[i][j][e] = 0.f;

    if (tid == 0) {
#pragma unroll
        for (int s = 0; s < STAGES; s++) mbar_init(smem_u32(&bbar[s]), 1);
    }
    __syncthreads();

#pragma unroll
    for (int s = 0; s < STAGES - 1; ++s) {
        uint32_t st = sbase + s * STAGE_BYTES;
        CP16(st + sA0, ag0 + s * 32);
        CP16(st + sA1, ag1 + s * 32);
        CP_COMMIT();
        if (tid == 0) {
            uint32_t mb = smem_u32(&bbar[s]);
            mbar_expect(mb, B_STAGE);
            bulk_ld(st + A_STAGE, Btiles + (size_t)s * 4096, B_STAGE, mb);
        }
    }

    const int sw = (g >> 1) & 3;
    for (int t = 0; t < nkt; ++t) {
        CP_WAIT(STAGES - 2);
        mbar_wait(smem_u32(&bbar[t & 3]), (t >> 2) & 1);
        __syncthreads();
        const int tn = t + STAGES - 1;
        if (tn < nkt) {
            uint32_t st = sbase + (tn & 3) * STAGE_BYTES;
            CP16(st + sA0, ag0 + tn * 32);
            CP16(st + sA1, ag1 + tn * 32);
            CP_COMMIT();
            if (tid == 0) {
                uint32_t mb = smem_u32(&bbar[tn & 3]);
                mbar_expect(mb, B_STAGE);
                bulk_ld(st + A_STAGE, Btiles + (size_t)tn * 4096, B_STAGE, mb);
            }
        }
        const uint32_t* As_ = (const uint32_t*)(smem_raw + (t & 3) * STAGE_BYTES);
        const uint32_t* Bs_ = (const uint32_t*)(smem_raw + (t & 3) * STAGE_BYTES + A_STAGE);
#pragma unroll
        for (int kb = 0; kb < 16; kb += 8) {
            const int ch0 = kb >> 2;          // 0 or 2
            uint32_t af[4][4], bf[4][2];
#pragma unroll
            for (int mt = 0; mt < 4; ++mt) {
                int base = (wm * 64 + mt * 16 + g) * 20 + kb + t4;
                af[mt][0] = As_[base];
                af[mt][1] = As_[base + 160];
                af[mt][2] = As_[base + 4];
                af[mt][3] = As_[base + 164];
            }
#pragma unroll
            for (int nt = 0; nt < 4; ++nt) {
                int rbase = (wn * 32 + nt * 8 + g) * 16 + t4;
                bf[nt][0] = Bs_[rbase + ((ch0 ^ sw) << 2)];
                bf[nt][1] = Bs_[rbase + (((ch0 + 1) ^ sw) << 2)];
            }
#pragma unroll
            for (int mt = 0; mt < 4; ++mt)
#pragma unroll
                for (int nt = 0; nt < 4; ++nt)
                    mma_f16(acc[mt][nt], af[mt], bf[nt]);
        }
    }

#pragma unroll
    for (int mt = 0; mt < 4; ++mt) {
        int r0 = brow + wm * 64 + mt * 16 + g;
#pragma unroll
        for (int nt = 0; nt < 4; ++nt) {
            int c0 = bcol + wn * 32 + nt * 8 + t4 * 2;
            float2 v0 = make_float2(acc[mt][nt][0], acc[mt][nt][1]);
            float2 v1 = make_float2(acc[mt][nt][2], acc[mt][nt][3]);
            if (MODE == 2) {
                __half* A16 = (__half*)Cv;
                int j0 = c0 >> 1;
                float a0 = v0.x / (1.f + __expf(-v0.x)) * v0.y;
                float a1 = v1.x / (1.f + __expf(-v1.x)) * v1.y;
                A16[(size_t)r0 * ldc + j0]       = __float2half(a0);
                A16[(size_t)(r0 + 8) * ldc + j0] = __float2half(a1);
            } else {
                if (bias) {
                    float2 bv = *(const float2*)&bias[c0];
                    v0.x += bv.x; v0.y += bv.y; v1.x += bv.x; v1.y += bv.y;
                }
                if (MODE == 1) {
                    __half* C16 = (__half*)Cv;
                    *(uint32_t*)&C16[(size_t)r0 * ldc + c0]       = pack_h2(v0.x, v0.y);
                    *(uint32_t*)&C16[(size_t)(r0 + 8) * ldc + c0] = pack_h2(v1.x, v1.y);
                } else {
                    float* C = (float*)Cv;
                    if (res) {
                        float2 ra = *(const float2*)&res[(size_t)r0 * ldc + c0];
                        float2 rb = *(const float2*)&res[(size_t)(r0 + 8) * ldc + c0];
                        v0.x += ra.x; v0.y += ra.y; v1.x += rb.x; v1.y += rb.y;
                    }
                    *(float2*)&C[(size_t)r0 * ldc + c0]       = v0;
                    *(float2*)&C[(size_t)(r0 + 8) * ldc + c0] = v1;
                }
            }
        }
    }
}

__global__ __launch_bounds__(256, 2)
void gemm_f16(const __half* __restrict__ A, const __half* __restrict__ B,
              const float* __restrict__ bias, const float* __restrict__ res,
              float* __restrict__ C, int ldc, int K) {
    gemm_core<0>(A, B, bias, res, C, ldc, K);
}
__global__ __launch_bounds__(256, 2)
void gemm_f16_qkv(const __half* __restrict__ A, const __half* __restrict__ B,
                  const float* __restrict__ bias, __half* __restrict__ C, int ldc, int K) {
    gemm_core<1>(A, B, bias, nullptr, C, ldc, K);
}
__global__ __launch_bounds__(256, 2)
void gemm_f16_silu(const __half* __restrict__ A, const __half* __restrict__ B,
                   __half* __restrict__ C, int ldc, int K) {
    gemm_core<2>(A, B, nullptr, nullptr, C, ldc, K);
}

// ---------------- fp32 -> fp16 TILED weight convert ----------------
// src row-major [N][K]; dst tiles [nb][kt] of 128x32 halves, chunk-swizzled.
__global__ void cvtw_tiled(const float* __restrict__ src, __half* __restrict__ dst,
                           int K, int nkt, int nofs, int n8) {
    int i = blockIdx.x * blockDim.x + threadIdx.x;
    if (i >= n8) return;
    int Kc = K >> 3;
    int n = nofs + i / Kc;
    int k = (i % Kc) * 8;
    float4 a = ((const float4*)src)[2 * i];
    float4 b = ((const float4*)src)[2 * i + 1];
    uint4 o;
    o.x = pack_h2(a.x, a.y); o.y = pack_h2(a.z, a.w);
    o.z = pack_h2(b.x, b.y); o.w = pack_h2(b.z, b.w);
    int nb = n >> 7, rn = n & 127, kt = k >> 5, cc = (k & 31) >> 3;
    ((uint4*)dst)[((size_t)(nb * nkt + kt) * 128 + rn) * 4 + (cc ^ ((rn >> 1) & 3))] = o;
}
// gate/up interleaved + tiled: src row j -> logical row 2j+off
__global__ void cvtw_gu_tiled(const float* __restrict__ wg, const float* __restrict__ wu,
                              __half* __restrict__ dst, int K, int nkt, int n8) {
    int i = blockIdx.x * blockDim.x + threadIdx.x;
    int off = 0;
    const float* src = wg;
    if (i >= n8) { i -= n8; off = 1; src = wu; }
    if (i >= n8) return;
    int Kc = K >> 3;
    int row = i / Kc;
    int k = (i % Kc) * 8;
    float4 a = ((const float4*)src)[2 * i];
    float4 b = ((const float4*)src)[2 * i + 1];
    uint4 o;
    o.x = pack_h2(a.x, a.y); o.y = pack_h2(a.z, a.w);
    o.z = pack_h2(b.x, b.y); o.w = pack_h2(b.z, b.w);
    int n = 2 * row + off;
    int nb = n >> 7, rn = n & 127, kt = k >> 5, cc = (k & 31) >> 3;
    ((uint4*)dst)[((size_t)(nb * nkt + kt) * 128 + rn) * 4 + (cc ^ ((rn >> 1) & 3))] = o;
}

__global__ void pack_bias_kernel(const float* __restrict__ bq, const float* __restrict__ bk,
                                 const float* __restrict__ bv, float* __restrict__ dst) {
    int i = blockIdx.x * blockDim.x + threadIdx.x;
    if (i < QKV_LD)
        dst[i] = (i < 2048) ? bq[i] : ((i < 2560) ? bk[i - 2048] : bv[i - 2560]);
}

// ---------------- RMSNorm -> fp16 ----------------
__global__ void rmsnorm16_kernel(const float* __restrict__ x, const float* __restrict__ w,
                                 __half* __restrict__ out) {
    int row = blockIdx.x;
    const float* xr = x + (size_t)row * HIDN;
    float4 v[2];
    float ss = 0.f;
#pragma unroll
    for (int i = 0; i < 2; i++) {
        v[i] = *(const float4*)&xr[(threadIdx.x + i * 256) * 4];
        ss += v[i].x * v[i].x + v[i].y * v[i].y + v[i].z * v[i].z + v[i].w * v[i].w;
    }
#pragma unroll
    for (int o = 16; o; o >>= 1) ss += __shfl_xor_sync(~0u, ss, o);
    __shared__ float red[8];
    if ((threadIdx.x & 31) == 0) red[threadIdx.x >> 5] = ss;
    __syncthreads();
    if (threadIdx.x == 0) {
        float t = 0.f;
#pragma unroll
        for (int i = 0; i < 8; i++) t += red[i];
        red[0] = rsqrtf(t / (float)HIDN + EPSV);
    }
    __syncthreads();
    float r = red[0];
#pragma unroll
    for (int i = 0; i < 2; i++) {
        int c = (threadIdx.x + i * 256) * 4;
        float4 wv = *(const float4*)&w[c];
        uint2 o2;
        o2.x = pack_h2(v[i].x * r * wv.x, v[i].y * r * wv.y);
        o2.y = pack_h2(v[i].z * r * wv.z, v[i].w * r * wv.w);
        *(uint2*)&out[(size_t)row * HIDN + c] = o2;
    }
}

// ---------------- per-head RMSNorm + RoPE on fp16 qkv (q pre-scaled) ----------------
__global__ void qknorm_rope16_kernel(__half* __restrict__ qkv,
                                     const float* __restrict__ qw, const float* __restrict__ kw,
                                     const float* __restrict__ cs, const float* __restrict__ sn) {
    int token = blockIdx.x, h = blockIdx.y;
    __half* p; const float* w; float oscale;
    if (h < NH) { p = qkv + (size_t)token * QKV_LD + h * HD;               w = qw; oscale = QK_SCALE; }
    else        { p = qkv + (size_t)token * QKV_LD + 2048 + (h - NH) * HD; w = kw; oscale = 1.f; }
    int d = threadIdx.x;
    float v = __half2float(p[d]);
    float ss = v * v;
#pragma unroll
    for (int o = 16; o; o >>= 1) ss += __shfl_xor_sync(~0u, ss, o);
    __shared__ float red[4];
    __shared__ float sh[128];
    if ((d & 31) == 0) red[d >> 5] = ss;
    __syncthreads();
    float tot = red[0] + red[1] + red[2] + red[3];
    float r = rsqrtf(tot / 128.f + EPSV);
    float xn = v * r * w[d];
    sh[d] = xn;
    __syncthreads();
    float rot = (d < 64) ? -sh[d + 64] : sh[d - 64];
    float c = cs[(size_t)token * 128 + d], s = sn[(size_t)token * 128 + d];
    p[d] = __float2half((xn * c + rot * s) * oscale);
}

// ---------------- flash attention (fp16 MMA, Q-tile 128, causal, GQA) ----------------
#define AQK_STRIDE 68
#define AV_STRIDE  136
#define AP_STRIDE  36
#define ATTN_U32  (128*AQK_STRIDE + 64*AQK_STRIDE + 32*AV_STRIDE + 128*AP_STRIDE + 2*128 + 2*128 + 3*128)
#define ATTN_SMEM_BYTES (ATTN_U32 * 4)

__global__ __launch_bounds__(512, 1)
void attn_kernel(const __half* __restrict__ qkv, __half* __restrict__ o16) {
    extern __shared__ uint32_t smem[];
    uint32_t* Qs = smem;
    uint32_t* Ks = Qs + 128 * AQK_STRIDE;
    uint32_t* Vs = Ks + 64 * AQK_STRIDE;
    uint32_t* Ps = Vs + 32 * AV_STRIDE;
    float* Pmax = (float*)(Ps + 128 * AP_STRIDE);
    float* Psum = Pmax + 256;
    float* Mrow = Psum + 256;
    float* Lrow = Mrow + 128;
    float* Arow = Lrow + 128;

    const int tid  = threadIdx.x;
    const int lane = tid & 31, warp = tid >> 5;
    const int wm = warp & 7, wn = warp >> 3;
    const int g = lane >> 2, t4 = lane & 3;
    const int qt = blockIdx.x, hq = blockIdx.y, b = blockIdx.z;
    const int kvh = hq >> 2;
    const int tok0 = b * SEQ + qt * 128;
    const int r0 = wm * 16 + g, r1 = r0 + 8;

    for (int l = tid; l < 128 * 16; l += 512) {
        int r = l >> 4, c = (l & 15);
        uint4 qv = *(const uint4*)&qkv[(size_t)(tok0 + r) * QKV_LD + hq * HD + c * 8];
        *(uint4*)&Qs[r * AQK_STRIDE + c * 4] = qv;
    }
    if (tid < 128) { Mrow[tid] = -3.0e38f; Lrow[tid] = 0.f; }

    float O[8][4];
#pragma unroll
    for (int nt = 0; nt < 8; nt++)
#pragma unroll
        for (int e = 0; e < 4; e++) O[nt][e] = 0.f;
    __syncthreads();

    const int nkt = 2 * qt + 2;
    for (int kt = 0; kt < nkt; ++kt) {
        for (int l = tid; l < 64 * 16; l += 512) {
            int r = l >> 4, c = (l & 15);
            uint4 kv = *(const uint4*)&qkv[(size_t)(b * SEQ + kt * 64 + r) * QKV_LD + 2048 + kvh * HD + c * 8];
            *(uint4*)&Ks[r * AQK_STRIDE + c * 4] = kv;
        }
        for (int l = tid; l < 32 * 16; l += 512) {
            int r = l >> 4, c = (l & 15);
            size_t base = (size_t)(b * SEQ + kt * 64 + 2 * r) * QKV_LD + 2560 + kvh * HD + c * 8;
            uint4 va = *(const uint4*)&qkv[base];
            uint4 vb = *(const uint4*)&qkv[base + QKV_LD];
            uint4 o0, o1;
            o0.x = __byte_perm(va.x, vb.x, 0x5410); o0.y = __byte_perm(va.x, vb.x, 0x7632);
            o0.z = __byte_perm(va.y, vb.y, 0x5410); o0.w = __byte_perm(va.y, vb.y, 0x7632);
            o1.x = __byte_perm(va.z, vb.z, 0x5410); o1.y = __byte_perm(va.z, vb.z, 0x7632);
            o1.z = __byte_perm(va.w, vb.w, 0x5410); o1.w = __byte_perm(va.w, vb.w, 0x7632);
            *(uint4*)&Vs[r * AV_STRIDE + c * 8]     = o0;
            *(uint4*)&Vs[r * AV_STRIDE + c * 8 + 4] = o1;
        }
        __syncthreads();

        float s[4][4];
#pragma unroll
        for (int nt = 0; nt < 4; nt++)
#pragma unroll
            for (int e = 0; e < 4; e++) s[nt][e] = 0.f;
        {
            const int arow0 = r0 * AQK_STRIDE, arow1 = r1 * AQK_STRIDE;
#pragma unroll
            for (int kb = 0; kb < 64; kb += 8) {
                uint32_t a[4];
                a[0] = Qs[arow0 + kb + t4];
                a[1] = Qs[arow1 + kb + t4];
                a[2] = Qs[arow0 + kb + t4 + 4];
                a[3] = Qs[arow1 + kb + t4 + 4];
#pragma unroll
                for (int nt = 0; nt < 4; nt++) {
                    uint32_t bb[2];
                    int nb = (wn * 32 + nt * 8 + g) * AQK_STRIDE + kb + t4;
                    bb[0] = Ks[nb]; bb[1] = Ks[nb + 4];
                    mma_f16(s[nt], a, bb);
                }
            }
        }

        if (kt >= 2 * qt) {
            const int dq = (2 * qt - kt) * 64;
#pragma unroll
            for (int nt = 0; nt < 4; nt++) {
                int c0 = wn * 32 + nt * 8 + 2 * t4;
                if (c0     > r0 + dq) s[nt][0] = -1.0e30f;
                if (c0 + 1 > r0 + dq) s[nt][1] = -1.0e30f;
                if (c0     > r1 + dq) s[nt][2] = -1.0e30f;
                if (c0 + 1 > r1 + dq) s[nt][3] = -1.0e30f;
            }
        }

        {
            float mx0 = fmaxf(fmaxf(s[0][0], s[0][1]), fmaxf(s[1][0], s[1][1]));
            mx0 = fmaxf(mx0, fmaxf(fmaxf(s[2][0], s[2][1]), fmaxf(s[3][0], s[3][1])));
            float mx1 = fmaxf(fmaxf(s[0][2], s[0][3]), fmaxf(s[1][2], s[1][3]));
            mx1 = fmaxf(mx1, fmaxf(fmaxf(s[2][2], s[2][3]), fmaxf(s[3][2], s[3][3])));
            mx0 = fmaxf(mx0, __shfl_xor_sync(~0u, mx0, 1));
            mx0 = fmaxf(mx0, __shfl_xor_sync(~0u, mx0, 2));
            mx1 = fmaxf(mx1, __shfl_xor_sync(~0u, mx1, 1));
            mx1 = fmaxf(mx1, __shfl_xor_sync(~0u, mx1, 2));
            if (t4 == 0) { Pmax[wn * 128 + r0] = mx0; Pmax[wn * 128 + r1] = mx1; }
        }
        __syncthreads();

        {
            float mn0 = fmaxf(Mrow[r0], fmaxf(Pmax[r0], Pmax[128 + r0]));
            float mn1 = fmaxf(Mrow[r1], fmaxf(Pmax[r1], Pmax[128 + r1]));
            float sum0 = 0.f, sum1 = 0.f;
#pragma unroll
            for (int nt = 0; nt < 4; nt++) {
                int cu = wn * 16 + nt * 4 + t4;
                float p0 = __expf(s[nt][0] - mn0);
                float p1 = __expf(s[nt][1] - mn0);
                float p2 = __expf(s[nt][2] - mn1);
                float p3 = __expf(s[nt][3] - mn1);
                sum0 += p0 + p1; sum1 += p2 + p3;
                Ps[r0 * AP_STRIDE + cu] = pack_h2(p0, p1);
                Ps[r1 * AP_STRIDE + cu] = pack_h2(p2, p3);
            }
            sum0 += __shfl_xor_sync(~0u, sum0, 1);
            sum0 += __shfl_xor_sync(~0u, sum0, 2);
            sum1 += __shfl_xor_sync(~0u, sum1, 1);
            sum1 += __shfl_xor_sync(~0u, sum1, 2);
            if (t4 == 0) { Psum[wn * 128 + r0] = sum0; Psum[wn * 128 + r1] = sum1; }
        }
        __syncthreads();

        if (tid < 128) {
            int r = tid;
            float mo = Mrow[r];
            float mn = fmaxf(mo, fmaxf(Pmax[r], Pmax[128 + r]));
            float al = __expf(mo - mn);
            Lrow[r] = Lrow[r] * al + Psum[r] + Psum[128 + r];
            Mrow[r] = mn;
            Arow[r] = al;
        }
        __syncthreads();

        {
            float al0 = Arow[r0], al1 = Arow[r1];
#pragma unroll
            for (int nt = 0; nt < 8; nt++) {
                O[nt][0] *= al0; O[nt][1] *= al0;
                O[nt][2] *= al1; O[nt][3] *= al1;
            }
            const int prow0 = r0 * AP_STRIDE, prow1 = r1 * AP_STRIDE;
#pragma unroll
            for (int kb = 0; kb < 32; kb += 8) {
                uint32_t a[4];
                a[0] = Ps[prow0 + kb + t4];
                a[1] = Ps[prow1 + kb + t4];
                a[2] = Ps[prow0 + kb + t4 + 4];
                a[3] = Ps[prow1 + kb + t4 + 4];
#pragma unroll
                for (int nt = 0; nt < 8; nt++) {
                    uint32_t bb[2];
                    int col = wn * 64 + nt * 8 + g;
                    bb[0] = Vs[(kb + t4) * AV_STRIDE + col];
                    bb[1] = Vs[(kb + t4 + 4) * AV_STRIDE + col];
                    mma_f16(O[nt], a, bb);
                }
            }
        }
        __syncthreads();
    }

    {
        float inv0 = 1.f / Lrow[r0], inv1 = 1.f / Lrow[r1];
        size_t base0 = (size_t)(tok0 + r0) * (NH * HD) + hq * HD;
        size_t base1 = (size_t)(tok0 + r1) * (NH * HD) + hq * HD;
#pragma unroll
        for (int nt = 0; nt < 8; nt++) {
            int c = wn * 64 + nt * 8 + 2 * t4;
            *(uint32_t*)&o16[base0 + c] = pack_h2(O[nt][0] * inv0, O[nt][1] * inv0);
            *(uint32_t*)&o16[base1 + c] = pack_h2(O[nt][2] * inv1, O[nt][3] * inv1);
        }
    }
}

// ---------------- host orchestration ----------------
extern "C" void kernel_launch(void* const* d_in, const int* in_sizes, int n_in,
                              void* d_out, int out_size) {
    const float* x    = (const float*)d_in[0];
    const float* cosb = (const float*)d_in[2];
    const float* sinb = (const float*)d_in[3];
    const float* wq   = (const float*)d_in[4];
    const float* bq   = (const float*)d_in[5];
    const float* wk   = (const float*)d_in[6];
    const float* bk   = (const float*)d_in[7];
    const float* wv   = (const float*)d_in[8];
    const float* bv   = (const float*)d_in[9];
    const float* wo   = (const float*)d_in[10];
    const float* qnw  = (const float*)d_in[11];
    const float* knw  = (const float*)d_in[12];
    const float* ln1  = (const float*)d_in[13];
    const float* ln2  = (const float*)d_in[14];
    const float* wg   = (const float*)d_in[15];
    const float* wu   = (const float*)d_in[16];
    const float* wd   = (const float*)d_in[17];
    float* out = (float*)d_out;

    __half *h16, *attn16, *act16, *wqkv16, *wo16, *wgu16, *wd16, *qkv16;
    float *x1_, *bqkv;
    cudaGetSymbolAddress((void**)&h16,    g_h16);
    cudaGetSymbolAddress((void**)&attn16, g_attn16);
    cudaGetSymbolAddress((void**)&act16,  g_act16);
    cudaGetSymbolAddress((void**)&wqkv16, g_wqkv16);
    cudaGetSymbolAddress((void**)&wo16,   g_wo16);
    cudaGetSymbolAddress((void**)&wgu16,  g_wgu16);
    cudaGetSymbolAddress((void**)&wd16,   g_wd16);
    cudaGetSymbolAddress((void**)&qkv16,  g_qkv16);
    cudaGetSymbolAddress((void**)&x1_,    g_x1);
    cudaGetSymbolAddress((void**)&bqkv,   g_bqkv);

    cudaFuncSetAttribute(attn_kernel,   cudaFuncAttributeMaxDynamicSharedMemorySize, ATTN_SMEM_BYTES);
    cudaFuncSetAttribute(gemm_f16,      cudaFuncAttributeMaxDynamicSharedMemorySize, GEMM_SMEM_BYTES);
    cudaFuncSetAttribute(gemm_f16_qkv,  cudaFuncAttributeMaxDynamicSharedMemorySize, GEMM_SMEM_BYTES);
    cudaFuncSetAttribute(gemm_f16_silu, cudaFuncAttributeMaxDynamicSharedMemorySize, GEMM_SMEM_BYTES);

    // 0. weight conversion -> TILED fp16
    {
        const int T = 256;
        cvtw_tiled<<<(2048*2048/8 + T-1)/T, T>>>(wq, wqkv16, 2048, 64,    0, 2048*2048/8);
        cvtw_tiled<<<( 512*2048/8 + T-1)/T, T>>>(wk, wqkv16, 2048, 64, 2048,  512*2048/8);
        cvtw_tiled<<<( 512*2048/8 + T-1)/T, T>>>(wv, wqkv16, 2048, 64, 2560,  512*2048/8);
        cvtw_tiled<<<(2048*2048/8 + T-1)/T, T>>>(wo, wo16,   2048, 64,    0, 2048*2048/8);
        cvtw_gu_tiled<<<(2*8192*2048/8 + T-1)/T, T>>>(wg, wu, wgu16, 2048, 64, 8192*2048/8);
        cvtw_tiled<<<(2048*8192/8 + T-1)/T, T>>>(wd, wd16,   8192, 256,   0, 2048*8192/8);
        pack_bias_kernel<<<(QKV_LD + T-1)/T, T>>>(bq, bk, bv, bqkv);
    }

    // 1. h16 = (half) RMSNorm(x, ln1)
    rmsnorm16_kernel<<<TTOK, 256>>>(x, ln1, h16);
    // 2. packed QKV projection -> fp16
    gemm_f16_qkv<<<dim3(QKV_LD/128, TTOK/128), 256, GEMM_SMEM_BYTES>>>(h16, wqkv16, bqkv, qkv16, QKV_LD, HIDN);
    // 3. per-head RMSNorm + RoPE
    qknorm_rope16_kernel<<<dim3(TTOK, NH + NKV), 128>>>(qkv16, qnw, knw, cosb, sinb);
    // 4. causal flash attention (Q-tile 128, fp16 MMA)
    attn_kernel<<<dim3(SEQ/128, NH, BATCH), 512, ATTN_SMEM_BYTES>>>(qkv16, attn16);
    // 5. x1 = x + attn @ wo^T
    gemm_f16<<<dim3(HIDN/128, TTOK/128), 256, GEMM_SMEM_BYTES>>>(attn16, wo16, nullptr, x, x1_, HIDN, HIDN);
    // 6. h16 = (half) RMSNorm(x1, ln2)
    rmsnorm16_kernel<<<TTOK, 256>>>(x1_, ln2, h16);
    // 7. fused gate|up + silu -> act16
    gemm_f16_silu<<<dim3(2*INTERN/128, TTOK/128), 256, GEMM_SMEM_BYTES>>>(h16, wgu16, act16, INTERN, HIDN);
    // 8. out = x1 + act @ wd^T
    gemm_f16<<<dim3(HIDN/128, TTOK/128), 256, GEMM_SMEM_BYTES>>>(act16, wd16, nullptr, x1_, out, HIDN, INTERN);
}

// round 16
// speedup vs baseline: 1.3787x; 1.1529x over previous
#include <cuda_runtime.h>
#include <cuda_fp16.h>
#include <cstdint>

#define HIDN   2048
#define NH     16
#define NKV    4
#define HD     128
#define INTERN 8192
#define BATCH  4
#define SEQ    1024
#define TTOK   (BATCH*SEQ)
#define EPSV   1e-6f
#define QK_SCALE 0.08838834764831845f
#define QKV_LD (NH*HD + 2*NKV*HD)      /* 3072 */

// ---------------- scratch ----------------
// Activations consumed as GEMM-A are TILED: [mb][kt][128 rows][32 halves], 16B-chunk swizzled.
__device__ __half g_h16   [TTOK * HIDN];     // tiled, nkt=64
__device__ __half g_qkv16 [TTOK * QKV_LD];   // row-major (attention random access)
__device__ __half g_attn16[TTOK * HIDN];     // tiled, nkt=64
__device__ float  g_x1    [TTOK * HIDN];
__device__ __half g_act16 [TTOK * INTERN];   // tiled, nkt=256
// weights, TILED same layout
__device__ __half g_wqkv16[QKV_LD * HIDN];
__device__ __half g_wo16  [HIDN * HIDN];
__device__ __half g_wgu16 [2 * INTERN * HIDN];   // rows interleaved: g_j->2j, u_j->2j+1
__device__ __half g_wd16  [HIDN * INTERN];
__device__ float  g_bqkv  [QKV_LD];

// ---------------- helpers ----------------
__device__ __forceinline__ void mma_f16(float c[4], const uint32_t a[4], const uint32_t b[2]) {
    asm volatile("mma.sync.aligned.m16n8k16.row.col.f32.f16.f16.f32 "
        "{%0,%1,%2,%3}, {%4,%5,%6,%7}, {%8,%9}, {%0,%1,%2,%3};\n"
        : "+f"(c[0]), "+f"(c[1]), "+f"(c[2]), "+f"(c[3])
        : "r"(a[0]), "r"(a[1]), "r"(a[2]), "r"(a[3]), "r"(b[0]), "r"(b[1]));
}
__device__ __forceinline__ uint32_t pack_h2(float lo, float hi) {
    __half2 h = __floats2half2_rn(lo, hi);
    return *(uint32_t*)&h;
}
__device__ __forceinline__ uint32_t smem_u32(const void* p) {
    uint32_t a;
    asm("{ .reg .u64 t; cvta.to.shared.u64 t, %1; cvt.u32.u64 %0, t; }" : "=r"(a) : "l"(p));
    return a;
}
__device__ __forceinline__ void mbar_init(uint32_t a, uint32_t cnt) {
    asm volatile("mbarrier.init.shared.b64 [%0], %1;" :: "r"(a), "r"(cnt) : "memory");
}
__device__ __forceinline__ void mbar_expect(uint32_t a, uint32_t tx) {
    asm volatile("mbarrier.arrive.expect_tx.shared.b64 _, [%0], %1;" :: "r"(a), "r"(tx) : "memory");
}
__device__ __forceinline__ void mbar_wait(uint32_t a, uint32_t ph) {
    asm volatile("{\n\t.reg .pred P;\n"
        "LAB_%=:\n\t"
        "mbarrier.try_wait.parity.shared.b64 P, [%0], %1;\n\t"
        "@!P bra LAB_%=;\n\t}"
        :: "r"(a), "r"(ph) : "memory");
}
__device__ __forceinline__ void bulk_ld(uint32_t dst, const void* src, uint32_t bytes, uint32_t mbar) {
    asm volatile("cp.async.bulk.shared::cta.global.mbarrier::complete_tx::bytes [%0], [%1], %2, [%3];"
        :: "r"(dst), "l"(src), "r"(bytes), "r"(mbar) : "memory");
}

// ---------------- fp16 GEMM: all-bulk (tiled A + tiled B) ----------------
// MODE 0: float C (+bias)(+res). MODE 1: half C row-major (+bias). MODE 2: silu fuse -> tiled act.
#define STAGES 4
#define STAGE_BYTES 16384                        /* A 8KB + B 8KB */
#define GEMM_SMEM_BYTES (STAGES * STAGE_BYTES)   /* 65536 */

template<int MODE>
__device__ __forceinline__ void gemm_core(
    const __half* __restrict__ At, const __half* __restrict__ Bt,
    const float* __restrict__ bias, const float* __restrict__ res,
    void* __restrict__ Cv, int ldc, int K)
{
    extern __shared__ uint8_t smem_raw[];
    __shared__ uint64_t bbar[STAGES];
    const int tid  = threadIdx.x;
    const int lane = tid & 31, warp = tid >> 5;
    const int wm = warp & 1, wn = warp >> 1;
    const int g  = lane >> 2, t4 = lane & 3;
    const int brow = blockIdx.y << 7, bcol = blockIdx.x << 7;
    const int nkt = K >> 5;

    const __half* Atiles = At + (size_t)blockIdx.y * nkt * 4096;
    const __half* Btiles = Bt + (size_t)blockIdx.x * nkt * 4096;
    const uint32_t sbase = (uint32_t)__cvta_generic_to_shared(smem_raw);

    float acc[4][4][4];
#pragma unroll
    for (int i = 0; i < 4; i++)
#pragma unroll
        for (int j = 0; j < 4; j++)
#pragma unroll
            for (int e = 0; e < 4; e++) acc[i][j][e] = 0.f;

    if (tid == 0) {
#pragma unroll
        for (int s = 0; s < STAGES; s++) mbar_init(smem_u32(&bbar[s]), 1);
    }
    __syncthreads();

    if (tid == 0) {
#pragma unroll
        for (int s = 0; s < STAGES - 1; ++s) {
            uint32_t st = sbase + s * STAGE_BYTES;
            uint32_t mb = smem_u32(&bbar[s]);
            mbar_expect(mb, STAGE_BYTES);
            bulk_ld(st,        Atiles + (size_t)s * 4096, 8192, mb);
            bulk_ld(st + 8192, Btiles + (size_t)s * 4096, 8192, mb);
        }
    }

    const int sw = (g >> 1) & 3;
    for (int t = 0; t < nkt; ++t) {
        mbar_wait(smem_u32(&bbar[t & 3]), (t >> 2) & 1);
        __syncthreads();
        const int tn = t + STAGES - 1;
        if (tn < nkt && tid == 0) {
            uint32_t st = sbase + (tn & 3) * STAGE_BYTES;
            uint32_t mb = smem_u32(&bbar[tn & 3]);
            mbar_expect(mb, STAGE_BYTES);
            bulk_ld(st,        Atiles + (size_t)tn * 4096, 8192, mb);
            bulk_ld(st + 8192, Btiles + (size_t)tn * 4096, 8192, mb);
        }
        const uint32_t* As_ = (const uint32_t*)(smem_raw + (t & 3) * STAGE_BYTES);
        const uint32_t* Bs_ = As_ + 2048;
#pragma unroll
        for (int kb = 0; kb < 16; kb += 8) {
            const int ch0 = kb >> 2;          // 0 or 2
            uint32_t af[4][4], bf[4][2];
#pragma unroll
            for (int mt = 0; mt < 4; ++mt) {
                int ra0 = (wm * 64 + mt * 16 + g) * 16 + t4;
                int ra1 = ra0 + 8 * 16;
                af[mt][0] = As_[ra0 + ((ch0 ^ sw) << 2)];
                af[mt][1] = As_[ra1 + ((ch0 ^ sw) << 2)];
                af[mt][2] = As_[ra0 + (((ch0 + 1) ^ sw) << 2)];
                af[mt][3] = As_[ra1 + (((ch0 + 1) ^ sw) << 2)];
            }
#pragma unroll
            for (int nt = 0; nt < 4; ++nt) {
                int rbase = (wn * 32 + nt * 8 + g) * 16 + t4;
                bf[nt][0] = Bs_[rbase + ((ch0 ^ sw) << 2)];
                bf[nt][1] = Bs_[rbase + (((ch0 + 1) ^ sw) << 2)];
            }
#pragma unroll
            for (int mt = 0; mt < 4; ++mt)
#pragma unroll
                for (int nt = 0; nt < 4; ++nt)
                    mma_f16(acc[mt][nt], af[mt], bf[nt]);
        }
    }

#pragma unroll
    for (int mt = 0; mt < 4; ++mt) {
        int r0 = brow + wm * 64 + mt * 16 + g;
#pragma unroll
        for (int nt = 0; nt < 4; ++nt) {
            int c0 = bcol + wn * 32 + nt * 8 + t4 * 2;
            float2 v0 = make_float2(acc[mt][nt][0], acc[mt][nt][1]);
            float2 v1 = make_float2(acc[mt][nt][2], acc[mt][nt][3]);
            if (MODE == 2) {
                // interleaved cols: (v.x,v.y) = (gate_j, up_j), j0 = c0/2; write TILED act16
                __half* A16 = (__half*)Cv;
                int j0 = c0 >> 1;
                float a0 = v0.x / (1.f + __expf(-v0.x)) * v0.y;
                float a1 = v1.x / (1.f + __expf(-v1.x)) * v1.y;
                int mb = r0 >> 7, rn = r0 & 127;
                int kt = j0 >> 5, cc = (j0 & 31) >> 3, hi = j0 & 7;
                int swr = (rn >> 1) & 3;   // same for rn and rn+8
                size_t base = ((size_t)(mb * 256 + kt) * 128 + rn) * 32 + ((cc ^ swr) << 3) + hi;
                A16[base]            = __float2half(a0);
                A16[base + 8 * 32]   = __float2half(a1);   // rn+8: +8 rows * 32 halves
            } else if (MODE == 1) {
                if (bias) {
                    float2 bv = *(const float2*)&bias[c0];
                    v0.x += bv.x; v0.y += bv.y; v1.x += bv.x; v1.y += bv.y;
                }
                __half* C16 = (__half*)Cv;
                *(uint32_t*)&C16[(size_t)r0 * ldc + c0]       = pack_h2(v0.x, v0.y);
                *(uint32_t*)&C16[(size_t)(r0 + 8) * ldc + c0] = pack_h2(v1.x, v1.y);
            } else {
                float* C = (float*)Cv;
                if (bias) {
                    float2 bv = *(const float2*)&bias[c0];
                    v0.x += bv.x; v0.y += bv.y; v1.x += bv.x; v1.y += bv.y;
                }
                if (res) {
                    float2 ra = *(const float2*)&res[(size_t)r0 * ldc + c0];
                    float2 rb = *(const float2*)&res[(size_t)(r0 + 8) * ldc + c0];
                    v0.x += ra.x; v0.y += ra.y; v1.x += rb.x; v1.y += rb.y;
                }
                *(float2*)&C[(size_t)r0 * ldc + c0]       = v0;
                *(float2*)&C[(size_t)(r0 + 8) * ldc + c0] = v1;
            }
        }
    }
}

__global__ __launch_bounds__(256, 2)
void gemm_f16(const __half* __restrict__ A, const __half* __restrict__ B,
              const float* __restrict__ bias, const float* __restrict__ res,
              float* __restrict__ C, int ldc, int K) {
    gemm_core<0>(A, B, bias, res, C, ldc, K);
}
__global__ __launch_bounds__(256, 2)
void gemm_f16_qkv(const __half* __restrict__ A, const __half* __restrict__ B,
                  const float* __restrict__ bias, __half* __restrict__ C, int ldc, int K) {
    gemm_core<1>(A, B, bias, nullptr, C, ldc, K);
}
__global__ __launch_bounds__(256, 2)
void gemm_f16_silu(const __half* __restrict__ A, const __half* __restrict__ B,
                   __half* __restrict__ C, int ldc, int K) {
    gemm_core<2>(A, B, nullptr, nullptr, C, ldc, K);
}

// ---------------- fp32 -> fp16 TILED weight convert ----------------
__global__ void cvtw_tiled(const float* __restrict__ src, __half* __restrict__ dst,
                           int K, int nkt, int nofs, int n8) {
    int i = blockIdx.x * blockDim.x + threadIdx.x;
    if (i >= n8) return;
    int Kc = K >> 3;
    int n = nofs + i / Kc;
    int k = (i % Kc) * 8;
    float4 a = ((const float4*)src)[2 * i];
    float4 b = ((const float4*)src)[2 * i + 1];
    uint4 o;
    o.x = pack_h2(a.x, a.y); o.y = pack_h2(a.z, a.w);
    o.z = pack_h2(b.x, b.y); o.w = pack_h2(b.z, b.w);
    int nb = n >> 7, rn = n & 127, kt = k >> 5, cc = (k & 31) >> 3;
    ((uint4*)dst)[((size_t)(nb * nkt + kt) * 128 + rn) * 4 + (cc ^ ((rn >> 1) & 3))] = o;
}
__global__ void cvtw_gu_tiled(const float* __restrict__ wg, const float* __restrict__ wu,
                              __half* __restrict__ dst, int K, int nkt, int n8) {
    int i = blockIdx.x * blockDim.x + threadIdx.x;
    int off = 0;
    const float* src = wg;
    if (i >= n8) { i -= n8; off = 1; src = wu; }
    if (i >= n8) return;
    int Kc = K >> 3;
    int row = i / Kc;
    int k = (i % Kc) * 8;
    float4 a = ((const float4*)src)[2 * i];
    float4 b = ((const float4*)src)[2 * i + 1];
    uint4 o;
    o.x = pack_h2(a.x, a.y); o.y = pack_h2(a.z, a.w);
    o.z = pack_h2(b.x, b.y); o.w = pack_h2(b.z, b.w);
    int n = 2 * row + off;
    int nb = n >> 7, rn = n & 127, kt = k >> 5, cc = (k & 31) >> 3;
    ((uint4*)dst)[((size_t)(nb * nkt + kt) * 128 + rn) * 4 + (cc ^ ((rn >> 1) & 3))] = o;
}

__global__ void pack_bias_kernel(const float* __restrict__ bq, const float* __restrict__ bk,
                                 const float* __restrict__ bv, float* __restrict__ dst) {
    int i = blockIdx.x * blockDim.x + threadIdx.x;
    if (i < QKV_LD)
        dst[i] = (i < 2048) ? bq[i] : ((i < 2560) ? bk[i - 2048] : bv[i - 2560]);
}

// ---------------- RMSNorm -> fp16 TILED (nkt=64) ----------------
__global__ void rmsnorm16_kernel(const float* __restrict__ x, const float* __restrict__ w,
                                 __half* __restrict__ out) {
    int row = blockIdx.x;
    const float* xr = x + (size_t)row * HIDN;
    // thread tid handles cols 8*tid .. 8*tid+7
    float4 v0 = ((const float4*)xr)[threadIdx.x * 2];
    float4 v1 = ((const float4*)xr)[threadIdx.x * 2 + 1];
    float ss = v0.x*v0.x + v0.y*v0.y + v0.z*v0.z + v0.w*v0.w
             + v1.x*v1.x + v1.y*v1.y + v1.z*v1.z + v1.w*v1.w;
#pragma unroll
    for (int o = 16; o; o >>= 1) ss += __shfl_xor_sync(~0u, ss, o);
    __shared__ float red[8];
    if ((threadIdx.x & 31) == 0) red[threadIdx.x >> 5] = ss;
    __syncthreads();
    if (threadIdx.x == 0) {
        float t = 0.f;
#pragma unroll
        for (int i = 0; i < 8; i++) t += red[i];
        red[0] = rsqrtf(t / (float)HIDN + EPSV);
    }
    __syncthreads();
    float r = red[0];
    float4 w0 = ((const float4*)w)[threadIdx.x * 2];
    float4 w1 = ((const float4*)w)[threadIdx.x * 2 + 1];
    uint4 o;
    o.x = pack_h2(v0.x * r * w0.x, v0.y * r * w0.y);
    o.y = pack_h2(v0.z * r * w0.z, v0.w * r * w0.w);
    o.z = pack_h2(v1.x * r * w1.x, v1.y * r * w1.y);
    o.w = pack_h2(v1.z * r * w1.z, v1.w * r * w1.w);
    int mb = row >> 7, rn = row & 127;
    int kt = threadIdx.x >> 2, cc = threadIdx.x & 3;
    ((uint4*)out)[((size_t)(mb * 64 + kt) * 128 + rn) * 4 + (cc ^ ((rn >> 1) & 3))] = o;
}

// ---------------- per-head RMSNorm + RoPE on fp16 qkv (q pre-scaled) ----------------
__global__ void qknorm_rope16_kernel(__half* __restrict__ qkv,
                                     const float* __restrict__ qw, const float* __restrict__ kw,
                                     const float* __restrict__ cs, const float* __restrict__ sn) {
    int token = blockIdx.x, h = blockIdx.y;
    __half* p; const float* w; float oscale;
    if (h < NH) { p = qkv + (size_t)token * QKV_LD + h * HD;               w = qw; oscale = QK_SCALE; }
    else        { p = qkv + (size_t)token * QKV_LD + 2048 + (h - NH) * HD; w = kw; oscale = 1.f; }
    int d = threadIdx.x;
    float v = __half2float(p[d]);
    float ss = v * v;
#pragma unroll
    for (int o = 16; o; o >>= 1) ss += __shfl_xor_sync(~0u, ss, o);
    __shared__ float red[4];
    __shared__ float sh[128];
    if ((d & 31) == 0) red[d >> 5] = ss;
    __syncthreads();
    float tot = red[0] + red[1] + red[2] + red[3];
    float r = rsqrtf(tot / 128.f + EPSV);
    float xn = v * r * w[d];
    sh[d] = xn;
    __syncthreads();
    float rot = (d < 64) ? -sh[d + 64] : sh[d - 64];
    float c = cs[(size_t)token * 128 + d], s = sn[(size_t)token * 128 + d];
    p[d] = __float2half((xn * c + rot * s) * oscale);
}

// ---------------- flash attention (fp16 MMA, Q-tile 128, causal, GQA) ----------------
// epilogue writes attn16 TILED (nkt=64)
#define AQK_STRIDE 68
#define AV_STRIDE  136
#define AP_STRIDE  36
#define ATTN_U32  (128*AQK_STRIDE + 64*AQK_STRIDE + 32*AV_STRIDE + 128*AP_STRIDE + 2*128 + 2*128 + 3*128)
#define ATTN_SMEM_BYTES (ATTN_U32 * 4)

__global__ __launch_bounds__(512, 1)
void attn_kernel(const __half* __restrict__ qkv, __half* __restrict__ o16) {
    extern __shared__ uint32_t smem[];
    uint32_t* Qs = smem;
    uint32_t* Ks = Qs + 128 * AQK_STRIDE;
    uint32_t* Vs = Ks + 64 * AQK_STRIDE;
    uint32_t* Ps = Vs + 32 * AV_STRIDE;
    float* Pmax = (float*)(Ps + 128 * AP_STRIDE);
    float* Psum = Pmax + 256;
    float* Mrow = Psum + 256;
    float* Lrow = Mrow + 128;
    float* Arow = Lrow + 128;

    const int tid  = threadIdx.x;
    const int lane = tid & 31, warp = tid >> 5;
    const int wm = warp & 7, wn = warp >> 3;
    const int g = lane >> 2, t4 = lane & 3;
    const int qt = blockIdx.x, hq = blockIdx.y, b = blockIdx.z;
    const int kvh = hq >> 2;
    const int tok0 = b * SEQ + qt * 128;
    const int r0 = wm * 16 + g, r1 = r0 + 8;

    for (int l = tid; l < 128 * 16; l += 512) {
        int r = l >> 4, c = (l & 15);
        uint4 qv = *(const uint4*)&qkv[(size_t)(tok0 + r) * QKV_LD + hq * HD + c * 8];
        *(uint4*)&Qs[r * AQK_STRIDE + c * 4] = qv;
    }
    if (tid < 128) { Mrow[tid] = -3.0e38f; Lrow[tid] = 0.f; }

    float O[8][4];
#pragma unroll
    for (int nt = 0; nt < 8; nt++)
#pragma unroll
        for (int e = 0; e < 4; e++) O[nt][e] = 0.f;
    __syncthreads();

    const int nkt = 2 * qt + 2;
    for (int kt = 0; kt < nkt; ++kt) {
        for (int l = tid; l < 64 * 16; l += 512) {
            int r = l >> 4, c = (l & 15);
            uint4 kv = *(const uint4*)&qkv[(size_t)(b * SEQ + kt * 64 + r) * QKV_LD + 2048 + kvh * HD + c * 8];
            *(uint4*)&Ks[r * AQK_STRIDE + c * 4] = kv;
        }
        for (int l = tid; l < 32 * 16; l += 512) {
            int r = l >> 4, c = (l & 15);
            size_t base = (size_t)(b * SEQ + kt * 64 + 2 * r) * QKV_LD + 2560 + kvh * HD + c * 8;
            uint4 va = *(const uint4*)&qkv[base];
            uint4 vb = *(const uint4*)&qkv[base + QKV_LD];
            uint4 o0, o1;
            o0.x = __byte_perm(va.x, vb.x, 0x5410); o0.y = __byte_perm(va.x, vb.x, 0x7632);
            o0.z = __byte_perm(va.y, vb.y, 0x5410); o0.w = __byte_perm(va.y, vb.y, 0x7632);
            o1.x = __byte_perm(va.z, vb.z, 0x5410); o1.y = __byte_perm(va.z, vb.z, 0x7632);
            o1.z = __byte_perm(va.w, vb.w, 0x5410); o1.w = __byte_perm(va.w, vb.w, 0x7632);
            *(uint4*)&Vs[r * AV_STRIDE + c * 8]     = o0;
            *(uint4*)&Vs[r * AV_STRIDE + c * 8 + 4] = o1;
        }
        __syncthreads();

        float s[4][4];
#pragma unroll
        for (int nt = 0; nt < 4; nt++)
#pragma unroll
            for (int e = 0; e < 4; e++) s[nt][e] = 0.f;
        {
            const int arow0 = r0 * AQK_STRIDE, arow1 = r1 * AQK_STRIDE;
#pragma unroll
            for (int kb = 0; kb < 64; kb += 8) {
                uint32_t a[4];
                a[0] = Qs[arow0 + kb + t4];
                a[1] = Qs[arow1 + kb + t4];
                a[2] = Qs[arow0 + kb + t4 + 4];
                a[3] = Qs[arow1 + kb + t4 + 4];
#pragma unroll
                for (int nt = 0; nt < 4; nt++) {
                    uint32_t bb[2];
                    int nb = (wn * 32 + nt * 8 + g) * AQK_STRIDE + kb + t4;
                    bb[0] = Ks[nb]; bb[1] = Ks[nb + 4];
                    mma_f16(s[nt], a, bb);
                }
            }
        }

        if (kt >= 2 * qt) {
            const int dq = (2 * qt - kt) * 64;
#pragma unroll
            for (int nt = 0; nt < 4; nt++) {
                int c0 = wn * 32 + nt * 8 + 2 * t4;
                if (c0     > r0 + dq) s[nt][0] = -1.0e30f;
                if (c0 + 1 > r0 + dq) s[nt][1] = -1.0e30f;
                if (c0     > r1 + dq) s[nt][2] = -1.0e30f;
                if (c0 + 1 > r1 + dq) s[nt][3] = -1.0e30f;
            }
        }

        {
            float mx0 = fmaxf(fmaxf(s[0][0], s[0][1]), fmaxf(s[1][0], s[1][1]));
            mx0 = fmaxf(mx0, fmaxf(fmaxf(s[2][0], s[2][1]), fmaxf(s[3][0], s[3][1])));
            float mx1 = fmaxf(fmaxf(s[0][2], s[0][3]), fmaxf(s[1][2], s[1][3]));
            mx1 = fmaxf(mx1, fmaxf(fmaxf(s[2][2], s[2][3]), fmaxf(s[3][2], s[3][3])));
            mx0 = fmaxf(mx0, __shfl_xor_sync(~0u, mx0, 1));
            mx0 = fmaxf(mx0, __shfl_xor_sync(~0u, mx0, 2));
            mx1 = fmaxf(mx1, __shfl_xor_sync(~0u, mx1, 1));
            mx1 = fmaxf(mx1, __shfl_xor_sync(~0u, mx1, 2));
            if (t4 == 0) { Pmax[wn * 128 + r0] = mx0; Pmax[wn * 128 + r1] = mx1; }
        }
        __syncthreads();

        {
            float mn0 = fmaxf(Mrow[r0], fmaxf(Pmax[r0], Pmax[128 + r0]));
            float mn1 = fmaxf(Mrow[r1], fmaxf(Pmax[r1], Pmax[128 + r1]));
            float sum0 = 0.f, sum1 = 0.f;
#pragma unroll
            for (int nt = 0; nt < 4; nt++) {
                int cu = wn * 16 + nt * 4 + t4;
                float p0 = __expf(s[nt][0] - mn0);
                float p1 = __expf(s[nt][1] - mn0);
                float p2 = __expf(s[nt][2] - mn1);
                float p3 = __expf(s[nt][3] - mn1);
                sum0 += p0 + p1; sum1 += p2 + p3;
                Ps[r0 * AP_STRIDE + cu] = pack_h2(p0, p1);
                Ps[r1 * AP_STRIDE + cu] = pack_h2(p2, p3);
            }
            sum0 += __shfl_xor_sync(~0u, sum0, 1);
            sum0 += __shfl_xor_sync(~0u, sum0, 2);
            sum1 += __shfl_xor_sync(~0u, sum1, 1);
            sum1 += __shfl_xor_sync(~0u, sum1, 2);
            if (t4 == 0) { Psum[wn * 128 + r0] = sum0; Psum[wn * 128 + r1] = sum1; }
        }
        __syncthreads();

        if (tid < 128) {
            int r = tid;
            float mo = Mrow[r];
            float mn = fmaxf(mo, fmaxf(Pmax[r], Pmax[128 + r]));
            float al = __expf(mo - mn);
            Lrow[r] = Lrow[r] * al + Psum[r] + Psum[128 + r];
            Mrow[r] = mn;
            Arow[r] = al;
        }
        __syncthreads();

        {
            float al0 = Arow[r0], al1 = Arow[r1];
#pragma unroll
            for (int nt = 0; nt < 8; nt++) {
                O[nt][0] *= al0; O[nt][1] *= al0;
                O[nt][2] *= al1; O[nt][3] *= al1;
            }
            const int prow0 = r0 * AP_STRIDE, prow1 = r1 * AP_STRIDE;
#pragma unroll
            for (int kb = 0; kb < 32; kb += 8) {
                uint32_t a[4];
                a[0] = Ps[prow0 + kb + t4];
                a[1] = Ps[prow1 + kb + t4];
                a[2] = Ps[prow0 + kb + t4 + 4];
                a[3] = Ps[prow1 + kb + t4 + 4];
#pragma unroll
                for (int nt = 0; nt < 8; nt++) {
                    uint32_t bb[2];
                    int col = wn * 64 + nt * 8 + g;
                    bb[0] = Vs[(kb + t4) * AV_STRIDE + col];
                    bb[1] = Vs[(kb + t4 + 4) * AV_STRIDE + col];
                    mma_f16(O[nt], a, bb);
                }
            }
        }
        __syncthreads();
    }

    // epilogue: write TILED attn16 (layout [mb][kt=64][128][32], chunk-swizzled)
    {
        float inv0 = 1.f / Lrow[r0], inv1 = 1.f / Lrow[r1];
        const int mb = tok0 >> 7;
        const int swr = (r0 >> 1) & 3;    // same for r0 and r1
#pragma unroll
        for (int nt = 0; nt < 8; nt++) {
            int n = hq * HD + wn * 64 + nt * 8 + 2 * t4;
            int kt = n >> 5, cc = (n & 31) >> 3, h2i = (n & 7) >> 1;
            size_t u = ((size_t)(mb * 64 + kt) * 128 + r0) * 16 + ((cc ^ swr) << 2) + h2i;
            ((uint32_t*)o16)[u]           = pack_h2(O[nt][0] * inv0, O[nt][1] * inv0);
            ((uint32_t*)o16)[u + 8 * 16]  = pack_h2(O[nt][2] * inv1, O[nt][3] * inv1);
        }
    }
}

// ---------------- host orchestration ----------------
extern "C" void kernel_launch(void* const* d_in, const int* in_sizes, int n_in,
                              void* d_out, int out_size) {
    const float* x    = (const float*)d_in[0];
    const float* cosb = (const float*)d_in[2];
    const float* sinb = (const float*)d_in[3];
    const float* wq   = (const float*)d_in[4];
    const float* bq   = (const float*)d_in[5];
    const float* wk   = (const float*)d_in[6];
    const float* bk   = (const float*)d_in[7];
    const float* wv   = (const float*)d_in[8];
    const float* bv   = (const float*)d_in[9];
    const float* wo   = (const float*)d_in[10];
    const float* qnw  = (const float*)d_in[11];
    const float* knw  = (const float*)d_in[12];
    const float* ln1  = (const float*)d_in[13];
    const float* ln2  = (const float*)d_in[14];
    const float* wg   = (const float*)d_in[15];
    const float* wu   = (const float*)d_in[16];
    const float* wd   = (const float*)d_in[17];
    float* out = (float*)d_out;

    __half *h16, *attn16, *act16, *wqkv16, *wo16, *wgu16, *wd16, *qkv16;
    float *x1_, *bqkv;
    cudaGetSymbolAddress((void**)&h16,    g_h16);
    cudaGetSymbolAddress((void**)&attn16, g_attn16);
    cudaGetSymbolAddress((void**)&act16,  g_act16);
    cudaGetSymbolAddress((void**)&wqkv16, g_wqkv16);
    cudaGetSymbolAddress((void**)&wo16,   g_wo16);
    cudaGetSymbolAddress((void**)&wgu16,  g_wgu16);
    cudaGetSymbolAddress((void**)&wd16,   g_wd16);
    cudaGetSymbolAddress((void**)&qkv16,  g_qkv16);
    cudaGetSymbolAddress((void**)&x1_,    g_x1);
    cudaGetSymbolAddress((void**)&bqkv,   g_bqkv);

    cudaFuncSetAttribute(attn_kernel,   cudaFuncAttributeMaxDynamicSharedMemorySize, ATTN_SMEM_BYTES);
    cudaFuncSetAttribute(gemm_f16,      cudaFuncAttributeMaxDynamicSharedMemorySize, GEMM_SMEM_BYTES);
    cudaFuncSetAttribute(gemm_f16_qkv,  cudaFuncAttributeMaxDynamicSharedMemorySize, GEMM_SMEM_BYTES);
    cudaFuncSetAttribute(gemm_f16_silu, cudaFuncAttributeMaxDynamicSharedMemorySize, GEMM_SMEM_BYTES);

    // 0. weight conversion -> TILED fp16
    {
        const int T = 256;
        cvtw_tiled<<<(2048*2048/8 + T-1)/T, T>>>(wq, wqkv16, 2048, 64,    0, 2048*2048/8);
        cvtw_tiled<<<( 512*2048/8 + T-1)/T, T>>>(wk, wqkv16, 2048, 64, 2048,  512*2048/8);
        cvtw_tiled<<<( 512*2048/8 + T-1)/T, T>>>(wv, wqkv16, 2048, 64, 2560,  512*2048/8);
        cvtw_tiled<<<(2048*2048/8 + T-1)/T, T>>>(wo, wo16,   2048, 64,    0, 2048*2048/8);
        cvtw_gu_tiled<<<(2*8192*2048/8 + T-1)/T, T>>>(wg, wu, wgu16, 2048, 64, 8192*2048/8);
        cvtw_tiled<<<(2048*8192/8 + T-1)/T, T>>>(wd, wd16,   8192, 256,   0, 2048*8192/8);
        pack_bias_kernel<<<(QKV_LD + T-1)/T, T>>>(bq, bk, bv, bqkv);
    }

    // 1. h16 = (half) RMSNorm(x, ln1)  [tiled]
    rmsnorm16_kernel<<<TTOK, 256>>>(x, ln1, h16);
    // 2. packed QKV projection -> fp16 row-major
    gemm_f16_qkv<<<dim3(QKV_LD/128, TTOK/128), 256, GEMM_SMEM_BYTES>>>(h16, wqkv16, bqkv, qkv16, QKV_LD, HIDN);
    // 3. per-head RMSNorm + RoPE
    qknorm_rope16_kernel<<<dim3(TTOK, NH + NKV), 128>>>(qkv16, qnw, knw, cosb, sinb);
    // 4. causal flash attention (Q-tile 128, fp16 MMA) -> tiled attn16
    attn_kernel<<<dim3(SEQ/128, NH, BATCH), 512, ATTN_SMEM_BYTES>>>(qkv16, attn16);
    // 5. x1 = x + attn @ wo^T
    gemm_f16<<<dim3(HIDN/128, TTOK/128), 256, GEMM_SMEM_BYTES>>>(attn16, wo16, nullptr, x, x1_, HIDN, HIDN);
    // 6. h16 = (half) RMSNorm(x1, ln2)  [tiled]
    rmsnorm16_kernel<<<TTOK, 256>>>(x1_, ln2, h16);
    // 7. fused gate|up + silu -> tiled act16
    gemm_f16_silu<<<dim3(2*INTERN/128, TTOK/128), 256, GEMM_SMEM_BYTES>>>(h16, wgu16, act16, INTERN, HIDN);
    // 8. out = x1 + act @ wd^T
    gemm_f16<<<dim3(HIDN/128, TTOK/128), 256, GEMM_SMEM_BYTES>>>(act16, wd16, nullptr, x1_, out, HIDN, INTERN);
}